// round 14
// baseline (speedup 1.0000x reference)
#include <cuda_runtime.h>
#include <cstdint>

#define RR 100
#define BB 8
#define IWW 64
#define DD 128
#define BDD 32
#define OWW 16

typedef unsigned long long ull;

// ---- packed fp32x2 helpers (sm_103a FFMA2 path, PTX-only) ----
__device__ __forceinline__ ull pk2(float lo, float hi) {
    ull r; asm("mov.b64 %0,{%1,%2};" : "=l"(r) : "f"(lo), "f"(hi)); return r;
}
__device__ __forceinline__ void upk2(float& lo, float& hi, ull v) {
    asm("mov.b64 {%0,%1},%2;" : "=f"(lo), "=f"(hi) : "l"(v));
}
__device__ __forceinline__ ull fma2(ull a, ull b, ull c) {
    ull d; asm("fma.rn.f32x2 %0,%1,%2,%3;" : "=l"(d) : "l"(a), "l"(b), "l"(c)); return d;
}
__device__ __forceinline__ ull add2(ull a, ull b) {
    ull d; asm("add.rn.f32x2 %0,%1,%2;" : "=l"(d) : "l"(a), "l"(b)); return d;
}

// Scratch (allocation-free rule: __device__ globals)
__device__ float g_q[BB * RR * DD];     // [b][r][d]
__device__ float g_K[BB * RR * DD];     // [b][r][d]
__device__ float g_Vn[BB * RR * BDD];   // [b][r][bd]
__device__ float g_attn[BB * RR * RR];  // [b][s][t]  (relu'd raw logits)

// Half-range packed linear: this thread sums k in [half*N/2, (half+1)*N/2).
template<int N>
__device__ __forceinline__ void lin2h(ull acc2[2], const float* __restrict__ W,
                                      int ldw, const ull x2[][2], int half) {
    const int H = N / 2;
    #pragma unroll
    for (int base = 0; base < H; base += 32) {
        float wb[32];
        #pragma unroll
        for (int u = 0; u < 32; u++)
            wb[u] = __ldg(W + (size_t)(half * H + base + u) * ldw);
        #pragma unroll
        for (int u = 0; u < 32; u++) {
            ull w2 = pk2(wb[u], wb[u]);
            acc2[0] = fma2(x2[half * H + base + u][0], w2, acc2[0]);
            acc2[1] = fma2(x2[half * H + base + u][1], w2, acc2[1]);
        }
    }
}

// Full-range packed linear with 32-deep load batching (for V-CTAs in kB).
template<int N>
__device__ __forceinline__ void lin2f(ull acc2[2], const float* __restrict__ W,
                                      int ldw, const ull x2[][2]) {
    #pragma unroll
    for (int base = 0; base < N; base += 32) {
        float wb[32];
        #pragma unroll
        for (int u = 0; u < 32; u++)
            wb[u] = __ldg(W + (size_t)(base + u) * ldw);
        #pragma unroll
        for (int u = 0; u < 32; u++) {
            ull w2 = pk2(wb[u], wb[u]);
            acc2[0] = fma2(x2[base + u][0], w2, acc2[0]);
            acc2[1] = fma2(x2[base + u][1], w2, acc2[1]);
        }
    }
}

// ---------------------------------------------------------------------------
// Kernel A: q + K embeddings only (V moved into kB). grid = (R, 2 paths,
// 2 batch-halves), 256 threads, k-dimension split across 2 thread-halves.
// ---------------------------------------------------------------------------
__global__ __launch_bounds__(256) void kA(
    const float* __restrict__ x, const float* __restrict__ mean,
    const float* __restrict__ stddev,
    const float* __restrict__ kv_in_W, const float* __restrict__ kv_in_b,
    const float* __restrict__ kv_blk_W, const float* __restrict__ kv_blk_b,
    const float* __restrict__ q_in_W, const float* __restrict__ q_in_b,
    const float* __restrict__ q_blk_W, const float* __restrict__ q_blk_b,
    const float* __restrict__ key_W, const float* __restrict__ key_b)
{
    int r = blockIdx.x;
    int path = blockIdx.y;        // 0 = q chain, 1 = kv->K chain
    int bh = blockIdx.z;          // batch half: batches [4*bh, 4*bh+4)
    int tid = threadIdx.x;
    int d = tid & 127, half = tid >> 7;

    __shared__ ull xn2[IWW][2];   // pair p packs batches (4bh+2p, 4bh+2p+1)
    __shared__ ull h2[DD][2];
    __shared__ ull spart[DD][2];

    float mu = mean[r];
    float isd = 1.0f / (stddev[r] + 1e-8f);
    if (tid < 128) {
        int i = tid & 63, p = tid >> 6;
        int b0 = 4 * bh + 2 * p;
        float a = (x[(b0 * RR + r) * IWW + i] - mu) * isd;
        float bb = (x[((b0 + 1) * RR + r) * IWW + i] - mu) * isd;
        xn2[i][p] = pk2(a, bb);
    }
    __syncthreads();

    ull acc2[2];

    if (path == 0) {
        // ---- Linear(IW->D) + ReLU ----
        acc2[0] = acc2[1] = 0ull;
        lin2h<IWW>(acc2, q_in_W + (size_t)r * IWW * DD + d, DD, xn2, half);
        if (!half) { spart[d][0] = acc2[0]; spart[d][1] = acc2[1]; }
        __syncthreads();
        if (half) {
            float bi = q_in_b[r * DD + d];
            #pragma unroll
            for (int p = 0; p < 2; p++) {
                float lo, hi; upk2(lo, hi, add2(acc2[p], spart[d][p]));
                h2[d][p] = pk2(fmaxf(lo + bi, 0.0f), fmaxf(hi + bi, 0.0f));
            }
        }
        __syncthreads();
        // ---- Linear(D->D) -> g_q ----
        acc2[0] = acc2[1] = 0ull;
        lin2h<DD>(acc2, q_blk_W + (size_t)r * DD * DD + d, DD, h2, half);
        if (!half) { spart[d][0] = acc2[0]; spart[d][1] = acc2[1]; }
        __syncthreads();
        if (half) {
            float bi = q_blk_b[r * DD + d];
            #pragma unroll
            for (int p = 0; p < 2; p++) {
                float lo, hi; upk2(lo, hi, add2(acc2[p], spart[d][p]));
                int b0 = 4 * bh + 2 * p;
                g_q[(b0 * RR + r) * DD + d] = lo + bi;
                g_q[((b0 + 1) * RR + r) * DD + d] = hi + bi;
            }
        }
        return;
    }

    // path 1: kv chain -> K
    acc2[0] = acc2[1] = 0ull;
    lin2h<IWW>(acc2, kv_in_W + d, DD, xn2, half);
    if (!half) { spart[d][0] = acc2[0]; spart[d][1] = acc2[1]; }
    __syncthreads();
    if (half) {
        float bi = kv_in_b[d];
        #pragma unroll
        for (int p = 0; p < 2; p++) {
            float lo, hi; upk2(lo, hi, add2(acc2[p], spart[d][p]));
            h2[d][p] = pk2(fmaxf(lo + bi, 0.0f), fmaxf(hi + bi, 0.0f));
        }
    }
    __syncthreads();

    acc2[0] = acc2[1] = 0ull;
    lin2h<DD>(acc2, kv_blk_W + d, DD, h2, half);
    if (!half) { spart[d][0] = acc2[0]; spart[d][1] = acc2[1]; }
    __syncthreads();
    if (half) {
        float bi = kv_blk_b[d];
        #pragma unroll
        for (int p = 0; p < 2; p++) {
            float lo, hi; upk2(lo, hi, add2(acc2[p], spart[d][p]));
            h2[d][p] = pk2(lo + bi, hi + bi);
        }
    }
    __syncthreads();

    // ---- K = kv @ key_W + key_b -> g_K ----
    acc2[0] = acc2[1] = 0ull;
    lin2h<DD>(acc2, key_W + d, DD, h2, half);
    if (!half) { spart[d][0] = acc2[0]; spart[d][1] = acc2[1]; }
    __syncthreads();
    if (half) {
        float bi = key_b[d];
        #pragma unroll
        for (int p = 0; p < 2; p++) {
            float lo, hi; upk2(lo, hi, add2(acc2[p], spart[d][p]));
            int b0 = 4 * bh + 2 * p;
            g_K[(b0 * RR + r) * DD + d] = lo + bi;
            g_K[((b0 + 1) * RR + r) * DD + d] = hi + bi;
        }
    }
}

// ---------------------------------------------------------------------------
// Kernel B: attention logits (round-10 stream, FROZEN) + 200 piggyback V-CTAs.
// blockIdx.y <  RR : one CTA per (s,t), software-pipelined W stream.
// blockIdx.y >= RR : V-path CTA for (r=blockIdx.x, bh=blockIdx.y-RR) — fully
// hidden under the DRAM-bound attention stream; produces g_Vn for kC.
// ---------------------------------------------------------------------------
__global__ __launch_bounds__(128) void kB(
    const float* __restrict__ qw, const float* __restrict__ qb,
    const float* __restrict__ x, const float* __restrict__ mean,
    const float* __restrict__ stddev,
    const float* __restrict__ kv_in_W, const float* __restrict__ kv_in_b,
    const float* __restrict__ kv_blk_W, const float* __restrict__ kv_blk_b,
    const float* __restrict__ value_W, const float* __restrict__ value_b)
{
    int tid = threadIdx.x;

    if (blockIdx.y >= RR) {
        // ---------------- V-path CTA ----------------
        int r = blockIdx.x;
        int bh = blockIdx.y - RR;      // 0 or 1

        __shared__ ull xn2v[IWW][2];
        __shared__ ull h2v[DD][2];
        __shared__ float kvsv[4][DD];

        float mu = mean[r];
        float isd = 1.0f / (stddev[r] + 1e-8f);
        {
            int i = tid & 63, p = tid >> 6;
            int b0 = 4 * bh + 2 * p;
            float a = (x[(b0 * RR + r) * IWW + i] - mu) * isd;
            float bb = (x[((b0 + 1) * RR + r) * IWW + i] - mu) * isd;
            xn2v[i][p] = pk2(a, bb);
        }
        __syncthreads();

        int d = tid;
        ull acc2[2];
        // kv_in (IW->D) + ReLU
        acc2[0] = acc2[1] = 0ull;
        lin2f<IWW>(acc2, kv_in_W + d, DD, xn2v);
        {
            float bi = kv_in_b[d];
            #pragma unroll
            for (int p = 0; p < 2; p++) {
                float lo, hi; upk2(lo, hi, acc2[p]);
                h2v[d][p] = pk2(fmaxf(lo + bi, 0.0f), fmaxf(hi + bi, 0.0f));
            }
        }
        __syncthreads();
        // kv_blk (D->D)
        acc2[0] = acc2[1] = 0ull;
        lin2f<DD>(acc2, kv_blk_W + d, DD, h2v);
        {
            float bi = kv_blk_b[d];
            #pragma unroll
            for (int p = 0; p < 2; p++) {
                float lo, hi; upk2(lo, hi, acc2[p]);
                kvsv[2 * p][d] = lo + bi;
                kvsv[2 * p + 1][d] = hi + bi;
            }
        }
        __syncthreads();
        // V = kv @ value_W + value_b; normalize. warp w = local batch w.
        {
            int w = tid >> 5, lane = tid & 31;
            float v = value_b[lane];
            const float* W = value_W + lane;
            #pragma unroll
            for (int base = 0; base < DD; base += 32) {
                float wb[32];
                #pragma unroll
                for (int u = 0; u < 32; u++)
                    wb[u] = __ldg(W + (size_t)(base + u) * BDD);
                #pragma unroll
                for (int u = 0; u < 32; u++)
                    v = fmaf(kvsv[w][base + u], wb[u], v);
            }
            float ss = v * v;
            #pragma unroll
            for (int o = 16; o > 0; o >>= 1)
                ss += __shfl_xor_sync(0xffffffffu, ss, o);
            int b = 4 * bh + w;
            g_Vn[(b * RR + r) * BDD + lane] = v / fmaxf(sqrtf(ss), 1e-12f);
        }
        return;
    }

    // ---------------- attention tile CTA (round-10, frozen) ----------------
    int t = blockIdx.x;
    int s = blockIdx.y;
    int w = tid >> 5, lane = tid & 31;
    int dbase = 4 * lane;

    __shared__ __align__(16) ull q2[DD][4];  // [i][pair]: (b=2p, b=2p+1)
    __shared__ __align__(16) ull k2[DD][4];
    __shared__ float sred[4][BB];

    {
        int d = tid;
        float qv[BB], kv[BB];
        #pragma unroll
        for (int b = 0; b < BB; b++) {
            qv[b] = g_q[(b * RR + s) * DD + d];
            kv[b] = g_K[(b * RR + t) * DD + d];
        }
        #pragma unroll
        for (int p = 0; p < 4; p++) {
            q2[d][p] = pk2(qv[2 * p], qv[2 * p + 1]);
            k2[d][p] = pk2(kv[2 * p], kv[2 * p + 1]);
        }
    }
    __syncthreads();

    ull acc2[4][4];
    #pragma unroll
    for (int c = 0; c < 4; c++)
        #pragma unroll
        for (int p = 0; p < 4; p++) acc2[c][p] = 0ull;

    const float* W = qw + ((size_t)(s * RR + t)) * DD * DD + (size_t)w * 32 * DD + dbase;

    float4 bufA[8], bufB[8];
    #pragma unroll
    for (int u = 0; u < 8; u++)
        bufA[u] = __ldcs(reinterpret_cast<const float4*>(W + (size_t)u * DD));

    #pragma unroll
    for (int batch = 0; batch < 4; batch++) {
        float4* cur = (batch & 1) ? bufB : bufA;
        float4* nxt = (batch & 1) ? bufA : bufB;
        if (batch < 3) {
            #pragma unroll
            for (int u = 0; u < 8; u++)
                nxt[u] = __ldcs(reinterpret_cast<const float4*>(
                    W + (size_t)((batch + 1) * 8 + u) * DD));
        }
        #pragma unroll
        for (int u = 0; u < 8; u++) {
            int i = w * 32 + batch * 8 + u;
            ulonglong2 qA = *reinterpret_cast<const ulonglong2*>(&q2[i][0]);
            ulonglong2 qB = *reinterpret_cast<const ulonglong2*>(&q2[i][2]);
            ull w0 = pk2(cur[u].x, cur[u].x);
            ull w1 = pk2(cur[u].y, cur[u].y);
            ull w2_ = pk2(cur[u].z, cur[u].z);
            ull w3 = pk2(cur[u].w, cur[u].w);
            acc2[0][0] = fma2(qA.x, w0, acc2[0][0]);
            acc2[0][1] = fma2(qA.y, w0, acc2[0][1]);
            acc2[0][2] = fma2(qB.x, w0, acc2[0][2]);
            acc2[0][3] = fma2(qB.y, w0, acc2[0][3]);
            acc2[1][0] = fma2(qA.x, w1, acc2[1][0]);
            acc2[1][1] = fma2(qA.y, w1, acc2[1][1]);
            acc2[1][2] = fma2(qB.x, w1, acc2[1][2]);
            acc2[1][3] = fma2(qB.y, w1, acc2[1][3]);
            acc2[2][0] = fma2(qA.x, w2_, acc2[2][0]);
            acc2[2][1] = fma2(qA.y, w2_, acc2[2][1]);
            acc2[2][2] = fma2(qB.x, w2_, acc2[2][2]);
            acc2[2][3] = fma2(qB.y, w2_, acc2[2][3]);
            acc2[3][0] = fma2(qA.x, w3, acc2[3][0]);
            acc2[3][1] = fma2(qA.y, w3, acc2[3][1]);
            acc2[3][2] = fma2(qB.x, w3, acc2[3][2]);
            acc2[3][3] = fma2(qB.y, w3, acc2[3][3]);
        }
    }

    ull pp[4];
    #pragma unroll
    for (int p = 0; p < 4; p++) pp[p] = 0ull;
    float4 b4 = __ldcs(reinterpret_cast<const float4*>(
        qb + ((size_t)(s * RR + t)) * DD + dbase));
    float bias[4] = {b4.x, b4.y, b4.z, b4.w};
    #pragma unroll
    for (int c = 0; c < 4; c++) {
        int dd = dbase + c;
        #pragma unroll
        for (int p = 0; p < 4; p++) {
            ull a = acc2[c][p];
            if (w == 0) a = add2(a, pk2(bias[c], bias[c]));
            pp[p] = fma2(a, k2[dd][p], pp[p]);
        }
    }
    float pf[BB];
    #pragma unroll
    for (int p = 0; p < 4; p++) upk2(pf[2 * p], pf[2 * p + 1], pp[p]);
    #pragma unroll
    for (int b = 0; b < BB; b++) {
        #pragma unroll
        for (int o = 16; o > 0; o >>= 1)
            pf[b] += __shfl_xor_sync(0xffffffffu, pf[b], o);
    }
    if (lane == 0) {
        #pragma unroll
        for (int b = 0; b < BB; b++) sred[w][b] = pf[b];
    }
    __syncthreads();
    if (tid < BB) {
        float l = sred[0][tid] + sred[1][tid] + sred[2][tid] + sred[3][tid];
        g_attn[(tid * RR + s) * RR + t] = fmaxf(l, 0.0f);
    }
}

// ---------------------------------------------------------------------------
// Kernel C: normalize attn, attn@Vn, reproj, post block, out proj, denorm.
// grid = (R, 2 batch-halves), 256 threads: reductions split across 2 halves.
// ---------------------------------------------------------------------------
__global__ __launch_bounds__(256) void kC(
    const float* __restrict__ reproj_W, const float* __restrict__ reproj_b,
    const float* __restrict__ post_blk_W, const float* __restrict__ post_blk_b,
    const float* __restrict__ out_W, const float* __restrict__ out_b,
    const float* __restrict__ mean, const float* __restrict__ stddev,
    float* __restrict__ out)
{
    int s = blockIdx.x;
    int bh = blockIdx.y;          // batches [4*bh, 4*bh+4)
    int tid = threadIdx.x;
    int d = tid & 127, half = tid >> 7;

    __shared__ float at[4][RR];
    __shared__ float ao[4][BDD];
    __shared__ float aopart[4][BDD];
    __shared__ __align__(16) ull ar2[DD][2];
    __shared__ ull rpart[DD][2];
    __shared__ float hs[4][DD];
    __shared__ float inv[4];
    __shared__ float opart[4][OWW];

    for (int idx = tid; idx < 4 * RR; idx += 256) {
        int b = idx / RR, t = idx % RR;
        at[b][t] = g_attn[((4 * bh + b) * RR + s) * RR + t];
    }
    __syncthreads();
    if (tid < 4) {
        float sum = 0.0f;
        #pragma unroll 10
        for (int t = 0; t < RR; t++) sum += at[tid][t];
        inv[tid] = 1.0f / (1e-8f + sum);
    }
    __syncthreads();

    // att_out: 256 threads = 4 batches x 32 bd x 2 t-halves (50 t's each)
    {
        int bd = tid & 31;
        int lb = (tid >> 5) & 3;
        int th = tid >> 7;
        int b = 4 * bh + lb;
        float a = 0.0f;
        const float* V = g_Vn + (size_t)(b * RR + th * 50) * BDD + bd;
        #pragma unroll 10
        for (int t = 0; t < 50; t++)
            a = fmaf(at[lb][th * 50 + t], V[(size_t)t * BDD], a);
        if (th == 0) aopart[lb][bd] = a;
        __syncthreads();
        if (th == 1) ao[lb][bd] = (a + aopart[lb][bd]) * inv[lb];
        __syncthreads();
    }

    // reproj (BD->D) + relu, k split 16/16 across halves, packed result
    {
        float acc[4];
        #pragma unroll
        for (int b = 0; b < 4; b++) acc[b] = 0.0f;
        const float* W = reproj_W + d;
        {
            float wb[16];
            #pragma unroll
            for (int u = 0; u < 16; u++)
                wb[u] = __ldg(W + (size_t)(half * 16 + u) * DD);
            #pragma unroll
            for (int u = 0; u < 16; u++)
                #pragma unroll
                for (int b = 0; b < 4; b++)
                    acc[b] = fmaf(ao[b][half * 16 + u], wb[u], acc[b]);
        }
        if (!half) {
            rpart[d][0] = pk2(acc[0], acc[1]);
            rpart[d][1] = pk2(acc[2], acc[3]);
        }
        __syncthreads();
        if (half) {
            float rb = reproj_b[d];
            #pragma unroll
            for (int p = 0; p < 2; p++) {
                float lo, hi; upk2(lo, hi, rpart[d][p]);
                ar2[d][p] = pk2(fmaxf(acc[2 * p] + lo + rb, 0.0f),
                                fmaxf(acc[2 * p + 1] + hi + rb, 0.0f));
            }
        }
        __syncthreads();
    }
    // post block (D->D), packed, k split 64/64 (one 32-batch x2 per half)
    {
        ull acc2[2];
        acc2[0] = acc2[1] = 0ull;
        const float* W = post_blk_W + (size_t)s * DD * DD + d;
        #pragma unroll
        for (int base = 0; base < 64; base += 32) {
            int j0 = half * 64 + base;
            float wb[32];
            #pragma unroll
            for (int u = 0; u < 32; u++) wb[u] = __ldg(W + (size_t)(j0 + u) * DD);
            #pragma unroll
            for (int u = 0; u < 32; u++) {
                ull w2 = pk2(wb[u], wb[u]);
                ulonglong2 aA = *reinterpret_cast<const ulonglong2*>(&ar2[j0 + u][0]);
                acc2[0] = fma2(aA.x, w2, acc2[0]);
                acc2[1] = fma2(aA.y, w2, acc2[1]);
            }
        }
        if (!half) { rpart[d][0] = acc2[0]; rpart[d][1] = acc2[1]; }
        __syncthreads();
        if (half) {
            float pb = post_blk_b[s * DD + d];
            #pragma unroll
            for (int p = 0; p < 2; p++) {
                float lo, hi; upk2(lo, hi, add2(acc2[p], rpart[d][p]));
                hs[2 * p][d] = lo + pb;
                hs[2 * p + 1][d] = hi + pb;
            }
        }
        __syncthreads();
    }
    // output projection (D->OW) + denorm; 128 threads = 4b x 16o x 2 d-halves
    if (tid < 128) {
        int o = tid & 15;
        int lb = (tid >> 4) & 3;
        int oh = tid >> 6;        // d-half
        float p = 0.0f;
        const float* W = out_W + (size_t)s * DD * OWW + o;
        #pragma unroll
        for (int base = 0; base < 64; base += 32) {
            int j0 = oh * 64 + base;
            float wb[32];
            #pragma unroll
            for (int u = 0; u < 32; u++) wb[u] = __ldg(W + (size_t)(j0 + u) * OWW);
            #pragma unroll
            for (int u = 0; u < 32; u++) p = fmaf(hs[lb][j0 + u], wb[u], p);
        }
        if (oh == 0) opart[lb][o] = p;
        __syncthreads();
        if (oh == 1) {
            int b = 4 * bh + lb;
            float res = p + opart[lb][o] + out_b[s * OWW + o];
            out[(b * RR + s) * OWW + o] = res * stddev[s] + mean[s];
        }
    } else {
        __syncthreads();
    }
}

extern "C" void kernel_launch(void* const* d_in, const int* in_sizes, int n_in,
                              void* d_out, int out_size)
{
    const float* x          = (const float*)d_in[0];
    const float* mean       = (const float*)d_in[1];
    const float* stddev     = (const float*)d_in[2];
    const float* kv_in_W    = (const float*)d_in[3];
    const float* kv_in_b    = (const float*)d_in[4];
    const float* kv_blk_W   = (const float*)d_in[5];
    const float* kv_blk_b   = (const float*)d_in[6];
    const float* q_in_W     = (const float*)d_in[7];
    const float* q_in_b     = (const float*)d_in[8];
    const float* q_blk_W    = (const float*)d_in[9];
    const float* q_blk_b    = (const float*)d_in[10];
    const float* key_W      = (const float*)d_in[11];
    const float* key_b      = (const float*)d_in[12];
    const float* value_W    = (const float*)d_in[13];
    const float* value_b    = (const float*)d_in[14];
    const float* qw         = (const float*)d_in[15];
    const float* qb         = (const float*)d_in[16];
    const float* reproj_W   = (const float*)d_in[17];
    const float* reproj_b   = (const float*)d_in[18];
    const float* post_blk_W = (const float*)d_in[19];
    const float* post_blk_b = (const float*)d_in[20];
    const float* out_W      = (const float*)d_in[21];
    const float* out_b      = (const float*)d_in[22];
    float* out = (float*)d_out;

    kA<<<dim3(RR, 2, 2), 256>>>(x, mean, stddev, kv_in_W, kv_in_b, kv_blk_W, kv_blk_b,
                                q_in_W, q_in_b, q_blk_W, q_blk_b,
                                key_W, key_b);
    kB<<<dim3(RR, RR + 2), 128>>>(qw, qb, x, mean, stddev,
                                  kv_in_W, kv_in_b, kv_blk_W, kv_blk_b,
                                  value_W, value_b);
    kC<<<dim3(RR, 2), 256>>>(reproj_W, reproj_b, post_blk_W, post_blk_b,
                             out_W, out_b, mean, stddev, out);
}

// round 15
// speedup vs baseline: 1.1576x; 1.1576x over previous
#include <cuda_runtime.h>
#include <cstdint>

#define RR 100
#define BB 8
#define IWW 64
#define DD 128
#define BDD 32
#define OWW 16

typedef unsigned long long ull;

// ---- packed fp32x2 helpers (sm_103a FFMA2 path, PTX-only) ----
__device__ __forceinline__ ull pk2(float lo, float hi) {
    ull r; asm("mov.b64 %0,{%1,%2};" : "=l"(r) : "f"(lo), "f"(hi)); return r;
}
__device__ __forceinline__ void upk2(float& lo, float& hi, ull v) {
    asm("mov.b64 {%0,%1},%2;" : "=f"(lo), "=f"(hi) : "l"(v));
}
__device__ __forceinline__ ull fma2(ull a, ull b, ull c) {
    ull d; asm("fma.rn.f32x2 %0,%1,%2,%3;" : "=l"(d) : "l"(a), "l"(b), "l"(c)); return d;
}
__device__ __forceinline__ ull add2(ull a, ull b) {
    ull d; asm("add.rn.f32x2 %0,%1,%2;" : "=l"(d) : "l"(a), "l"(b)); return d;
}

// ---- PDL (programmatic dependent launch) ----
__device__ __forceinline__ void gdc_wait() {
    asm volatile("griddepcontrol.wait;" ::: "memory");
}
__device__ __forceinline__ void gdc_launch() {
    asm volatile("griddepcontrol.launch_dependents;");
}

// Scratch (allocation-free rule: __device__ globals)
__device__ float g_q[BB * RR * DD];     // [b][r][d]
__device__ float g_K[BB * RR * DD];     // [b][r][d]
__device__ float g_Vn[BB * RR * BDD];   // [b][r][bd]
__device__ float g_attn[BB * RR * RR];  // [b][s][t]  (relu'd raw logits)

// Half-range packed linear: this thread sums k in [half*N/2, (half+1)*N/2).
template<int N>
__device__ __forceinline__ void lin2h(ull acc2[2], const float* __restrict__ W,
                                      int ldw, const ull x2[][2], int half) {
    const int H = N / 2;
    #pragma unroll
    for (int base = 0; base < H; base += 32) {
        float wb[32];
        #pragma unroll
        for (int u = 0; u < 32; u++)
            wb[u] = __ldg(W + (size_t)(half * H + base + u) * ldw);
        #pragma unroll
        for (int u = 0; u < 32; u++) {
            ull w2 = pk2(wb[u], wb[u]);
            acc2[0] = fma2(x2[half * H + base + u][0], w2, acc2[0]);
            acc2[1] = fma2(x2[half * H + base + u][1], w2, acc2[1]);
        }
    }
}

// ---------------------------------------------------------------------------
// Kernel A: per-region embeddings (round-13). grid = (R, 3 paths, 2 halves),
// 256 threads, k-dimension split across 2 thread-halves.
// ---------------------------------------------------------------------------
__global__ __launch_bounds__(256) void kA(
    const float* __restrict__ x, const float* __restrict__ mean,
    const float* __restrict__ stddev,
    const float* __restrict__ kv_in_W, const float* __restrict__ kv_in_b,
    const float* __restrict__ kv_blk_W, const float* __restrict__ kv_blk_b,
    const float* __restrict__ q_in_W, const float* __restrict__ q_in_b,
    const float* __restrict__ q_blk_W, const float* __restrict__ q_blk_b,
    const float* __restrict__ key_W, const float* __restrict__ key_b,
    const float* __restrict__ value_W, const float* __restrict__ value_b)
{
    int r = blockIdx.x;
    int path = blockIdx.y;
    int bh = blockIdx.z;          // batch half: batches [4*bh, 4*bh+4)
    int tid = threadIdx.x;
    int d = tid & 127, half = tid >> 7;

    __shared__ ull xn2[IWW][2];   // pair p packs batches (4bh+2p, 4bh+2p+1)
    __shared__ ull h2[DD][2];
    __shared__ ull spart[DD][2];
    __shared__ float kvs[4][DD];
    __shared__ float vp[4][2][BDD];

    float mu = mean[r];
    float isd = 1.0f / (stddev[r] + 1e-8f);
    if (tid < 128) {
        int i = tid & 63, p = tid >> 6;
        int b0 = 4 * bh + 2 * p;
        float a = (x[(b0 * RR + r) * IWW + i] - mu) * isd;
        float bb = (x[((b0 + 1) * RR + r) * IWW + i] - mu) * isd;
        xn2[i][p] = pk2(a, bb);
    }
    __syncthreads();

    ull acc2[2];

    if (path == 0) {
        // ---- Linear(IW->D) + ReLU ----
        acc2[0] = acc2[1] = 0ull;
        lin2h<IWW>(acc2, q_in_W + (size_t)r * IWW * DD + d, DD, xn2, half);
        if (!half) { spart[d][0] = acc2[0]; spart[d][1] = acc2[1]; }
        __syncthreads();
        if (half) {
            float bi = q_in_b[r * DD + d];
            #pragma unroll
            for (int p = 0; p < 2; p++) {
                float lo, hi; upk2(lo, hi, add2(acc2[p], spart[d][p]));
                h2[d][p] = pk2(fmaxf(lo + bi, 0.0f), fmaxf(hi + bi, 0.0f));
            }
        }
        __syncthreads();
        // ---- Linear(D->D) -> g_q ----
        acc2[0] = acc2[1] = 0ull;
        lin2h<DD>(acc2, q_blk_W + (size_t)r * DD * DD + d, DD, h2, half);
        if (!half) { spart[d][0] = acc2[0]; spart[d][1] = acc2[1]; }
        __syncthreads();
        if (half) {
            float bi = q_blk_b[r * DD + d];
            #pragma unroll
            for (int p = 0; p < 2; p++) {
                float lo, hi; upk2(lo, hi, add2(acc2[p], spart[d][p]));
                int b0 = 4 * bh + 2 * p;
                g_q[(b0 * RR + r) * DD + d] = lo + bi;
                g_q[((b0 + 1) * RR + r) * DD + d] = hi + bi;
            }
        }
        gdc_launch();
        return;
    }

    // paths 1 & 2: kv chain
    acc2[0] = acc2[1] = 0ull;
    lin2h<IWW>(acc2, kv_in_W + d, DD, xn2, half);
    if (!half) { spart[d][0] = acc2[0]; spart[d][1] = acc2[1]; }
    __syncthreads();
    if (half) {
        float bi = kv_in_b[d];
        #pragma unroll
        for (int p = 0; p < 2; p++) {
            float lo, hi; upk2(lo, hi, add2(acc2[p], spart[d][p]));
            h2[d][p] = pk2(fmaxf(lo + bi, 0.0f), fmaxf(hi + bi, 0.0f));
        }
    }
    __syncthreads();

    acc2[0] = acc2[1] = 0ull;
    lin2h<DD>(acc2, kv_blk_W + d, DD, h2, half);
    if (!half) { spart[d][0] = acc2[0]; spart[d][1] = acc2[1]; }
    __syncthreads();
    if (half) {
        float bi = kv_blk_b[d];
        #pragma unroll
        for (int p = 0; p < 2; p++) {
            float lo, hi; upk2(lo, hi, add2(acc2[p], spart[d][p]));
            lo += bi; hi += bi;
            h2[d][p] = pk2(lo, hi);
            if (path == 2) { kvs[2 * p][d] = lo; kvs[2 * p + 1][d] = hi; }
        }
    }
    __syncthreads();

    if (path == 1) {
        // ---- K = kv @ key_W + key_b -> g_K ----
        acc2[0] = acc2[1] = 0ull;
        lin2h<DD>(acc2, key_W + d, DD, h2, half);
        if (!half) { spart[d][0] = acc2[0]; spart[d][1] = acc2[1]; }
        __syncthreads();
        if (half) {
            float bi = key_b[d];
            #pragma unroll
            for (int p = 0; p < 2; p++) {
                float lo, hi; upk2(lo, hi, add2(acc2[p], spart[d][p]));
                int b0 = 4 * bh + 2 * p;
                g_K[(b0 * RR + r) * DD + d] = lo + bi;
                g_K[((b0 + 1) * RR + r) * DD + d] = hi + bi;
            }
        }
    } else {
        // ---- V = kv @ value_W + value_b; normalize -> g_Vn ----
        int w = tid >> 5, lane = tid & 31;
        int lb = w >> 1, vhalf = w & 1;
        float v = vhalf ? 0.0f : value_b[lane];
        const float* W = value_W + lane;
        #pragma unroll
        for (int base = 0; base < 64; base += 32) {
            int j0 = vhalf * 64 + base;
            float wb[32];
            #pragma unroll
            for (int u = 0; u < 32; u++) wb[u] = __ldg(W + (size_t)(j0 + u) * BDD);
            #pragma unroll
            for (int u = 0; u < 32; u++) v = fmaf(kvs[lb][j0 + u], wb[u], v);
        }
        vp[lb][vhalf][lane] = v;
        __syncthreads();
        if (w < 4) {
            float vv = vp[w][0][lane] + vp[w][1][lane];
            float ss = vv * vv;
            #pragma unroll
            for (int o = 16; o > 0; o >>= 1) ss += __shfl_xor_sync(0xffffffffu, ss, o);
            int b = 4 * bh + w;
            g_Vn[(b * RR + r) * BDD + lane] = vv / fmaxf(sqrtf(ss), 1e-12f);
        }
    }
    gdc_launch();
}

// ---------------------------------------------------------------------------
// Kernel B: attention logits (round-10 stream, FROZEN) + PDL: the bias load
// and first W-batch prefetch (independent of kA) issue BEFORE griddepcontrol
// wait, overlapping kA's tail for the first wave of CTAs.
// ---------------------------------------------------------------------------
__global__ __launch_bounds__(128) void kB(
    const float* __restrict__ qw, const float* __restrict__ qb)
{
    int t = blockIdx.x;
    int s = blockIdx.y;
    int tid = threadIdx.x;
    int w = tid >> 5, lane = tid & 31;
    int dbase = 4 * lane;

    __shared__ __align__(16) ull q2[DD][4];  // [i][pair]: (b=2p, b=2p+1)
    __shared__ __align__(16) ull k2[DD][4];
    __shared__ float sred[4][BB];

    const float* W = qw + ((size_t)(s * RR + t)) * DD * DD + (size_t)w * 32 * DD + dbase;

    // -------- independent prologue (before grid-dependency wait) --------
    float4 b4 = __ldcs(reinterpret_cast<const float4*>(
        qb + ((size_t)(s * RR + t)) * DD + dbase));
    float4 bufA[8], bufB[8];
    #pragma unroll
    for (int u = 0; u < 8; u++)
        bufA[u] = __ldcs(reinterpret_cast<const float4*>(W + (size_t)u * DD));

    gdc_wait();   // g_q / g_K ready beyond this point

    {
        int d = tid;
        float qv[BB], kv[BB];
        #pragma unroll
        for (int b = 0; b < BB; b++) {
            qv[b] = g_q[(b * RR + s) * DD + d];
            kv[b] = g_K[(b * RR + t) * DD + d];
        }
        #pragma unroll
        for (int p = 0; p < 4; p++) {
            q2[d][p] = pk2(qv[2 * p], qv[2 * p + 1]);
            k2[d][p] = pk2(kv[2 * p], kv[2 * p + 1]);
        }
    }
    __syncthreads();

    ull acc2[4][4];
    #pragma unroll
    for (int c = 0; c < 4; c++)
        #pragma unroll
        for (int p = 0; p < 4; p++) acc2[c][p] = 0ull;

    #pragma unroll
    for (int batch = 0; batch < 4; batch++) {
        float4* cur = (batch & 1) ? bufB : bufA;
        float4* nxt = (batch & 1) ? bufA : bufB;
        if (batch < 3) {
            #pragma unroll
            for (int u = 0; u < 8; u++)
                nxt[u] = __ldcs(reinterpret_cast<const float4*>(
                    W + (size_t)((batch + 1) * 8 + u) * DD));
        }
        #pragma unroll
        for (int u = 0; u < 8; u++) {
            int i = w * 32 + batch * 8 + u;
            ulonglong2 qA = *reinterpret_cast<const ulonglong2*>(&q2[i][0]);
            ulonglong2 qB = *reinterpret_cast<const ulonglong2*>(&q2[i][2]);
            ull w0 = pk2(cur[u].x, cur[u].x);
            ull w1 = pk2(cur[u].y, cur[u].y);
            ull w2_ = pk2(cur[u].z, cur[u].z);
            ull w3 = pk2(cur[u].w, cur[u].w);
            acc2[0][0] = fma2(qA.x, w0, acc2[0][0]);
            acc2[0][1] = fma2(qA.y, w0, acc2[0][1]);
            acc2[0][2] = fma2(qB.x, w0, acc2[0][2]);
            acc2[0][3] = fma2(qB.y, w0, acc2[0][3]);
            acc2[1][0] = fma2(qA.x, w1, acc2[1][0]);
            acc2[1][1] = fma2(qA.y, w1, acc2[1][1]);
            acc2[1][2] = fma2(qB.x, w1, acc2[1][2]);
            acc2[1][3] = fma2(qB.y, w1, acc2[1][3]);
            acc2[2][0] = fma2(qA.x, w2_, acc2[2][0]);
            acc2[2][1] = fma2(qA.y, w2_, acc2[2][1]);
            acc2[2][2] = fma2(qB.x, w2_, acc2[2][2]);
            acc2[2][3] = fma2(qB.y, w2_, acc2[2][3]);
            acc2[3][0] = fma2(qA.x, w3, acc2[3][0]);
            acc2[3][1] = fma2(qA.y, w3, acc2[3][1]);
            acc2[3][2] = fma2(qB.x, w3, acc2[3][2]);
            acc2[3][3] = fma2(qB.y, w3, acc2[3][3]);
        }
    }

    ull pp[4];
    #pragma unroll
    for (int p = 0; p < 4; p++) pp[p] = 0ull;
    float bias[4] = {b4.x, b4.y, b4.z, b4.w};
    #pragma unroll
    for (int c = 0; c < 4; c++) {
        int dd = dbase + c;
        #pragma unroll
        for (int p = 0; p < 4; p++) {
            ull a = acc2[c][p];
            if (w == 0) a = add2(a, pk2(bias[c], bias[c]));
            pp[p] = fma2(a, k2[dd][p], pp[p]);
        }
    }
    float pf[BB];
    #pragma unroll
    for (int p = 0; p < 4; p++) upk2(pf[2 * p], pf[2 * p + 1], pp[p]);
    #pragma unroll
    for (int b = 0; b < BB; b++) {
        #pragma unroll
        for (int o = 16; o > 0; o >>= 1)
            pf[b] += __shfl_xor_sync(0xffffffffu, pf[b], o);
    }
    if (lane == 0) {
        #pragma unroll
        for (int b = 0; b < BB; b++) sred[w][b] = pf[b];
    }
    __syncthreads();
    if (tid < BB) {
        float l = sred[0][tid] + sred[1][tid] + sred[2][tid] + sred[3][tid];
        g_attn[(tid * RR + s) * RR + t] = fmaxf(l, 0.0f);
    }
    gdc_launch();
}

// ---------------------------------------------------------------------------
// Kernel C: normalize attn, attn@Vn, reproj, post block, out proj, denorm.
// grid = (R, 2 batch-halves), 256 threads: reductions split across 2 halves.
// PDL: waits for kB before reading g_attn.
// ---------------------------------------------------------------------------
__global__ __launch_bounds__(256) void kC(
    const float* __restrict__ reproj_W, const float* __restrict__ reproj_b,
    const float* __restrict__ post_blk_W, const float* __restrict__ post_blk_b,
    const float* __restrict__ out_W, const float* __restrict__ out_b,
    const float* __restrict__ mean, const float* __restrict__ stddev,
    float* __restrict__ out)
{
    int s = blockIdx.x;
    int bh = blockIdx.y;          // batches [4*bh, 4*bh+4)
    int tid = threadIdx.x;
    int d = tid & 127, half = tid >> 7;

    __shared__ float at[4][RR];
    __shared__ float ao[4][BDD];
    __shared__ float aopart[4][BDD];
    __shared__ __align__(16) ull ar2[DD][2];
    __shared__ ull rpart[DD][2];
    __shared__ float hs[4][DD];
    __shared__ float inv[4];
    __shared__ float opart[4][OWW];

    gdc_wait();   // g_attn / g_Vn ready beyond this point

    for (int idx = tid; idx < 4 * RR; idx += 256) {
        int b = idx / RR, t = idx % RR;
        at[b][t] = g_attn[((4 * bh + b) * RR + s) * RR + t];
    }
    __syncthreads();
    if (tid < 4) {
        float sum = 0.0f;
        #pragma unroll 10
        for (int t = 0; t < RR; t++) sum += at[tid][t];
        inv[tid] = 1.0f / (1e-8f + sum);
    }
    __syncthreads();

    // att_out: 256 threads = 4 batches x 32 bd x 2 t-halves (50 t's each)
    {
        int bd = tid & 31;
        int lb = (tid >> 5) & 3;
        int th = tid >> 7;
        int b = 4 * bh + lb;
        float a = 0.0f;
        const float* V = g_Vn + (size_t)(b * RR + th * 50) * BDD + bd;
        #pragma unroll 10
        for (int t = 0; t < 50; t++)
            a = fmaf(at[lb][th * 50 + t], V[(size_t)t * BDD], a);
        if (th == 0) aopart[lb][bd] = a;
        __syncthreads();
        if (th == 1) ao[lb][bd] = (a + aopart[lb][bd]) * inv[lb];
        __syncthreads();
    }

    // reproj (BD->D) + relu, k split 16/16 across halves, packed result
    {
        float acc[4];
        #pragma unroll
        for (int b = 0; b < 4; b++) acc[b] = 0.0f;
        const float* W = reproj_W + d;
        {
            float wb[16];
            #pragma unroll
            for (int u = 0; u < 16; u++)
                wb[u] = __ldg(W + (size_t)(half * 16 + u) * DD);
            #pragma unroll
            for (int u = 0; u < 16; u++)
                #pragma unroll
                for (int b = 0; b < 4; b++)
                    acc[b] = fmaf(ao[b][half * 16 + u], wb[u], acc[b]);
        }
        if (!half) {
            rpart[d][0] = pk2(acc[0], acc[1]);
            rpart[d][1] = pk2(acc[2], acc[3]);
        }
        __syncthreads();
        if (half) {
            float rb = reproj_b[d];
            #pragma unroll
            for (int p = 0; p < 2; p++) {
                float lo, hi; upk2(lo, hi, rpart[d][p]);
                ar2[d][p] = pk2(fmaxf(acc[2 * p] + lo + rb, 0.0f),
                                fmaxf(acc[2 * p + 1] + hi + rb, 0.0f));
            }
        }
        __syncthreads();
    }
    // post block (D->D), packed, k split 64/64 (one 32-batch x2 per half)
    {
        ull acc2[2];
        acc2[0] = acc2[1] = 0ull;
        const float* W = post_blk_W + (size_t)s * DD * DD + d;
        #pragma unroll
        for (int base = 0; base < 64; base += 32) {
            int j0 = half * 64 + base;
            float wb[32];
            #pragma unroll
            for (int u = 0; u < 32; u++) wb[u] = __ldg(W + (size_t)(j0 + u) * DD);
            #pragma unroll
            for (int u = 0; u < 32; u++) {
                ull w2 = pk2(wb[u], wb[u]);
                ulonglong2 aA = *reinterpret_cast<const ulonglong2*>(&ar2[j0 + u][0]);
                acc2[0] = fma2(aA.x, w2, acc2[0]);
                acc2[1] = fma2(aA.y, w2, acc2[1]);
            }
        }
        if (!half) { rpart[d][0] = acc2[0]; rpart[d][1] = acc2[1]; }
        __syncthreads();
        if (half) {
            float pb = post_blk_b[s * DD + d];
            #pragma unroll
            for (int p = 0; p < 2; p++) {
                float lo, hi; upk2(lo, hi, add2(acc2[p], rpart[d][p]));
                hs[2 * p][d] = lo + pb;
                hs[2 * p + 1][d] = hi + pb;
            }
        }
        __syncthreads();
    }
    // output projection (D->OW) + denorm; 128 threads = 4b x 16o x 2 d-halves
    if (tid < 128) {
        int o = tid & 15;
        int lb = (tid >> 4) & 3;
        int oh = tid >> 6;        // d-half
        float p = 0.0f;
        const float* W = out_W + (size_t)s * DD * OWW + o;
        #pragma unroll
        for (int base = 0; base < 64; base += 32) {
            int j0 = oh * 64 + base;
            float wb[32];
            #pragma unroll
            for (int u = 0; u < 32; u++) wb[u] = __ldg(W + (size_t)(j0 + u) * OWW);
            #pragma unroll
            for (int u = 0; u < 32; u++) p = fmaf(hs[lb][j0 + u], wb[u], p);
        }
        if (oh == 0) opart[lb][o] = p;
        __syncthreads();
        if (oh == 1) {
            int b = 4 * bh + lb;
            float res = p + opart[lb][o] + out_b[s * OWW + o];
            out[(b * RR + s) * OWW + o] = res * stddev[s] + mean[s];
        }
    } else {
        __syncthreads();
    }
}

extern "C" void kernel_launch(void* const* d_in, const int* in_sizes, int n_in,
                              void* d_out, int out_size)
{
    const float* x          = (const float*)d_in[0];
    const float* mean       = (const float*)d_in[1];
    const float* stddev     = (const float*)d_in[2];
    const float* kv_in_W    = (const float*)d_in[3];
    const float* kv_in_b    = (const float*)d_in[4];
    const float* kv_blk_W   = (const float*)d_in[5];
    const float* kv_blk_b   = (const float*)d_in[6];
    const float* q_in_W     = (const float*)d_in[7];
    const float* q_in_b     = (const float*)d_in[8];
    const float* q_blk_W    = (const float*)d_in[9];
    const float* q_blk_b    = (const float*)d_in[10];
    const float* key_W      = (const float*)d_in[11];
    const float* key_b      = (const float*)d_in[12];
    const float* value_W    = (const float*)d_in[13];
    const float* value_b    = (const float*)d_in[14];
    const float* qw         = (const float*)d_in[15];
    const float* qb         = (const float*)d_in[16];
    const float* reproj_W   = (const float*)d_in[17];
    const float* reproj_b   = (const float*)d_in[18];
    const float* post_blk_W = (const float*)d_in[19];
    const float* post_blk_b = (const float*)d_in[20];
    const float* out_W      = (const float*)d_in[21];
    const float* out_b      = (const float*)d_in[22];
    float* out = (float*)d_out;

    kA<<<dim3(RR, 3, 2), 256>>>(x, mean, stddev, kv_in_W, kv_in_b, kv_blk_W, kv_blk_b,
                                q_in_W, q_in_b, q_blk_W, q_blk_b,
                                key_W, key_b, value_W, value_b);

    cudaLaunchAttribute pdl[1];
    pdl[0].id = cudaLaunchAttributeProgrammaticStreamSerialization;
    pdl[0].val.programmaticStreamSerializationAllowed = 1;

    {
        cudaLaunchConfig_t cfg = {};
        cfg.gridDim = dim3(RR, RR);
        cfg.blockDim = dim3(128);
        cfg.attrs = pdl;
        cfg.numAttrs = 1;
        cudaLaunchKernelEx(&cfg, kB, qw, qb);
    }
    {
        cudaLaunchConfig_t cfg = {};
        cfg.gridDim = dim3(RR, 2);
        cfg.blockDim = dim3(256);
        cfg.attrs = pdl;
        cfg.numAttrs = 1;
        cudaLaunchKernelEx(&cfg, kC, reproj_W, reproj_b, post_blk_W, post_blk_b,
                           out_W, out_b, mean, stddev, out);
    }
}